// round 13
// baseline (speedup 1.0000x reference)
#include <cuda_runtime.h>
#include <cuda_fp16.h>
#include <cuda_bf16.h>
#include <math.h>
#include <stdint.h>

// ---------------- problem constants ----------------
#define BB        4
#define LSEQ      2048
#define DMODEL    1024
#define DIN       2048          // D_INNER
#define NH        32            // NHEADS
#define HD        64            // HEADDIM
#define DSTATE    128
#define CONVDIM   2304          // DIN + 2*DSTATE
#define DPROJ     4384          // 2*DIN + 2*DSTATE + NH
#define MROWS     (BB*LSEQ)     // 8192

typedef unsigned long long ull;

// ---------------- scratch (static __device__, no allocs) ----------------
__device__ float g_zxbcdt[(size_t)MROWS * DPROJ];
__device__ float g_xc[(size_t)MROWS * CONVDIM];
__device__ float g_y[(size_t)MROWS * DIN];
__device__ float g_dt[(size_t)MROWS * NH];
__device__ float g_dA[(size_t)MROWS * NH];

// fp16 operands (single precision pass)
__device__ __half g_ah[(size_t)MROWS * DMODEL];     // hidden fp16
__device__ __half g_w1h[(size_t)DPROJ * DMODEL];    // W_in^T  [N][K]
__device__ __half g_yh[(size_t)MROWS * DIN];        // gated/normed y
__device__ __half g_w2h[(size_t)DMODEL * DIN];      // W_out^T [N][K]

// ---------------- f32x2 helpers ----------------
__device__ __forceinline__ ull ffma2(ull a, ull b, ull c) {
    ull d; asm("fma.rn.f32x2 %0, %1, %2, %3;" : "=l"(d) : "l"(a), "l"(b), "l"(c)); return d;
}
__device__ __forceinline__ ull fmul2(ull a, ull b) {
    ull d; asm("mul.rn.f32x2 %0, %1, %2;" : "=l"(d) : "l"(a), "l"(b)); return d;
}
__device__ __forceinline__ ull pack2(float lo, float hi) {
    ull r; asm("mov.b64 %0, {%1, %2};" : "=l"(r) : "f"(lo), "f"(hi)); return r;
}
__device__ __forceinline__ float2 unpack2(ull v) {
    float2 f; asm("mov.b64 {%0, %1}, %2;" : "=f"(f.x), "=f"(f.y) : "l"(v)); return f;
}

// ---------------- mma.sync / ldmatrix / cp.async helpers ----------------
__device__ __forceinline__ uint32_t smem_u32(const void* p) {
    uint32_t a;
    asm("{ .reg .u64 t; cvta.to.shared.u64 t, %1; cvt.u32.u64 %0, t; }" : "=r"(a) : "l"(p));
    return a;
}
__device__ __forceinline__ void ldsm4(uint32_t& r0, uint32_t& r1, uint32_t& r2, uint32_t& r3,
                                      uint32_t addr) {
    asm volatile("ldmatrix.sync.aligned.m8n8.x4.shared.b16 {%0,%1,%2,%3}, [%4];"
                 : "=r"(r0), "=r"(r1), "=r"(r2), "=r"(r3) : "r"(addr));
}
__device__ __forceinline__ void mma16816h(float* c, uint32_t a0, uint32_t a1, uint32_t a2,
                                          uint32_t a3, uint32_t b0, uint32_t b1) {
    asm volatile(
        "mma.sync.aligned.m16n8k16.row.col.f32.f16.f16.f32 "
        "{%0,%1,%2,%3}, {%4,%5,%6,%7}, {%8,%9}, {%0,%1,%2,%3};"
        : "+f"(c[0]), "+f"(c[1]), "+f"(c[2]), "+f"(c[3])
        : "r"(a0), "r"(a1), "r"(a2), "r"(a3), "r"(b0), "r"(b1));
}
__device__ __forceinline__ void cp16(uint32_t saddr, const void* gaddr, uint32_t srcbytes) {
    asm volatile("cp.async.cg.shared.global [%0], [%1], 16, %2;"
                 :: "r"(saddr), "l"(gaddr), "r"(srcbytes));
}
__device__ __forceinline__ void cp4(uint32_t saddr, const void* gaddr) {
    asm volatile("cp.async.ca.shared.global [%0], [%1], 4;"
                 :: "r"(saddr), "l"(gaddr));
}
__device__ __forceinline__ void cp_commit() { asm volatile("cp.async.commit_group;"); }
template <int N_> __device__ __forceinline__ void cp_wait() {
    asm volatile("cp.async.wait_group %0;" :: "n"(N_));
}

// ---------------- converters (fp32 -> fp16) ----------------
__global__ void __launch_bounds__(256)
convert_h(const float* __restrict__ src, __half* __restrict__ dst, int n4)
{
    int i = blockIdx.x * 256 + threadIdx.x;
    if (i >= n4) return;
    float4 v = ((const float4*)src)[i];
    __half2 h0; h0.x = __float2half(v.x); h0.y = __float2half(v.y);
    __half2 h1; h1.x = __float2half(v.z); h1.y = __float2half(v.w);
    ((__half2*)dst)[i*2]   = h0;
    ((__half2*)dst)[i*2+1] = h1;
}

// src [K][N] fp32 -> dstT [N][K] fp16
__global__ void __launch_bounds__(256)
transpose_h(const float* __restrict__ src, __half* __restrict__ dstT, int K, int N)
{
    __shared__ float t[32][33];
    const int kb = blockIdx.y * 32, nb = blockIdx.x * 32;
    const int tx = threadIdx.x & 31, ty = threadIdx.x >> 5;
#pragma unroll
    for (int j = 0; j < 4; j++)
        t[ty + j*8][tx] = src[(size_t)(kb + ty + j*8) * N + nb + tx];
    __syncthreads();
#pragma unroll
    for (int j = 0; j < 4; j++) {
        const int n = nb + ty + j*8, k = kb + tx;
        dstT[(size_t)n * K + k] = __float2half(t[tx][ty + j*8]);
    }
}

// ---------------- HMMA GEMM (frozen from R12 — measured 247us GEMM1) ---------
#define GS_STRIDE 144
#define GS_TILE   (128 * GS_STRIDE)   // 18432 B
#define GS_BUF    (2 * GS_TILE)       // A|B = 36864 B
#define GS_DYN    (2 * GS_BUF)        // 73728 B

__global__ void __launch_bounds__(256)
gemm_hmma(const __half* __restrict__ A, const __half* __restrict__ BT,
          float* __restrict__ C, int N, int K)
{
    extern __shared__ char smem[];
    const uint32_t sb = smem_u32(smem);

    const int tid = threadIdx.x;
    const int lane = tid & 31;
    const int wid = tid >> 5;
    const int warp_m = wid & 1;
    const int warp_n = wid >> 1;
    const int rowBase = blockIdx.y << 7;
    const int colBase = blockIdx.x << 7;
    const int nkc = K >> 6;               // BK = 64

    float acc[4][4][4];
#pragma unroll
    for (int i = 0; i < 4; i++)
#pragma unroll
        for (int j = 0; j < 4; j++)
#pragma unroll
            for (int q = 0; q < 4; q++) acc[i][j][q] = 0.f;

    auto load_chunk = [&](int kc, int buf) {
        const uint32_t base = sb + (uint32_t)buf * GS_BUF;
#pragma unroll
        for (int it = 0; it < 4; it++) {
            const int id = tid + it * 256;
            const int row = id >> 3, c = id & 7;
            const size_t g = (size_t)(rowBase + row) * K + kc * 64 + c * 8;
            cp16(base + (uint32_t)(row * GS_STRIDE + c * 16), A + g, 16);
        }
#pragma unroll
        for (int it = 0; it < 4; it++) {
            const int id = tid + it * 256;
            const int row = id >> 3, c = id & 7;
            const int n = colBase + row;
            const int nn = (n < N) ? n : 0;
            const uint32_t valid = (n < N) ? 16u : 0u;
            const size_t g = (size_t)nn * K + kc * 64 + c * 8;
            cp16(base + GS_TILE + (uint32_t)(row * GS_STRIDE + c * 16), BT + g, valid);
        }
    };

    load_chunk(0, 0);
    cp_commit();

    for (int kc = 0; kc < nkc; kc++) {
        const int buf = kc & 1;
        if (kc + 1 < nkc) {
            load_chunk(kc + 1, buf ^ 1);
            cp_commit();
            cp_wait<1>();
        } else {
            cp_wait<0>();
        }
        __syncthreads();

        const uint32_t aTb = sb + (uint32_t)buf * GS_BUF;
        const uint32_t bTb = aTb + GS_TILE;

#pragma unroll
        for (int ks = 0; ks < 4; ks++) {
            const uint32_t loff = (uint32_t)((lane & 15) * GS_STRIDE + (lane >> 4) * 16 + ks * 32);

            uint32_t aH[4][4];
#pragma unroll
            for (int mt = 0; mt < 4; mt++) {
                const uint32_t ro = (uint32_t)((warp_m * 64 + mt * 16) * GS_STRIDE) + loff;
                ldsm4(aH[mt][0], aH[mt][1], aH[mt][2], aH[mt][3], aTb + ro);
            }
            uint32_t bH[4][2];
#pragma unroll
            for (int np = 0; np < 2; np++) {
                const uint32_t ro = (uint32_t)((warp_n * 32 + np * 16) * GS_STRIDE) + loff;
                uint32_t r0, r1, r2, r3;
                ldsm4(r0, r1, r2, r3, bTb + ro);
                bH[np*2][0] = r0; bH[np*2][1] = r2;
                bH[np*2+1][0] = r1; bH[np*2+1][1] = r3;
            }
#pragma unroll
            for (int mt = 0; mt < 4; mt++)
#pragma unroll
                for (int nt = 0; nt < 4; nt++)
                    mma16816h(acc[mt][nt], aH[mt][0], aH[mt][1], aH[mt][2], aH[mt][3],
                              bH[nt][0], bH[nt][1]);
        }
        __syncthreads();
    }

    const int g = lane >> 2, tg = lane & 3;
#pragma unroll
    for (int mt = 0; mt < 4; mt++) {
#pragma unroll
        for (int nt = 0; nt < 4; nt++) {
            const int col = colBase + warp_n * 32 + nt * 8 + tg * 2;
            if (col < N) {
                const int r0 = rowBase + warp_m * 64 + mt * 16 + g;
                float2 v0 = make_float2(acc[mt][nt][0], acc[mt][nt][1]);
                float2 v1 = make_float2(acc[mt][nt][2], acc[mt][nt][3]);
                *(float2*)(C + (size_t)r0 * N + col)       = v0;
                *(float2*)(C + (size_t)(r0 + 8) * N + col) = v1;
            }
        }
    }
}

// ---------------- conv(4) + SiLU: 8 timesteps per CTA (sliding window) -------
__global__ void __launch_bounds__(256)
conv_kernel(const float* __restrict__ conv_w, const float* __restrict__ conv_b)
{
    const int bl0 = blockIdx.x * 8;
    const int l0  = bl0 & (LSEQ - 1);
    const int tid = threadIdx.x;
    const float* base = g_zxbcdt + (size_t)bl0 * DPROJ + DIN;
    float* out = g_xc + (size_t)bl0 * CONVDIM;

    for (int c = tid; c < CONVDIM; c += 256) {
        const float4 w = *(const float4*)(conv_w + c * 4);
        const float bias = conv_b[c];
        float v[11];
#pragma unroll
        for (int k = 0; k < 11; k++) {
            const int ll = l0 + k - 3;
            v[k] = (ll >= 0) ? base[(ptrdiff_t)(k - 3) * DPROJ + c] : 0.f;
        }
#pragma unroll
        for (int j = 0; j < 8; j++) {
            const float a = bias + w.x * v[j] + w.y * v[j+1] + w.z * v[j+2] + w.w * v[j+3];
            out[(size_t)j * CONVDIM + c] = a / (1.f + expf(-a));
        }
    }
}

// ---------------- dt / dA ----------------
__global__ void __launch_bounds__(256)
dt_kernel(const float* __restrict__ dt_bias, const float* __restrict__ A_log)
{
    const int idx = blockIdx.x * 256 + threadIdx.x;
    const int bl = idx >> 5, hh = idx & 31;
    const float v = g_zxbcdt[(size_t)bl * DPROJ + (DPROJ - NH) + hh] + dt_bias[hh];
    const float dtv = (v > 20.f) ? v : log1pf(expf(v));
    g_dt[idx] = dtv;
    g_dA[idx] = expf(-expf(A_log[hh]) * dtv);
}

// ---------------- selective scan: R9 mapping + register double-buffer --------
// 256 thr, 2p x 16n per thread. NEW: step j+1's B/C/x/dA/dt are prefetched into
// a second register set while step j computes, decoupling the fma chain from
// LDS latency so the MIO (LDS+shfl, ~304 cyc/step) and fma (192 cyc/step)
// pipes overlap instead of serializing (measured ~450 cyc/step at R9).
#define SC_STAGES 4
#define SC_STEPS  4
__global__ void __launch_bounds__(256)
scan_kernel(const float* __restrict__ Dv)
{
    const int h = blockIdx.x, b = blockIdx.y;
    const int tid = threadIdx.x;
    const int nc = tid & 7;
    const int pg = tid >> 3;
    const int p0 = pg * 2;

    const float* xc  = g_xc + (size_t)b * LSEQ * CONVDIM;
    const float* dAp = g_dA + (size_t)b * LSEQ * NH + h;
    const float* dtp = g_dt + (size_t)b * LSEQ * NH + h;
    float* yout = g_y + (size_t)b * LSEQ * DIN + h * HD + p0;

    __shared__ __align__(16) float sB[SC_STAGES][SC_STEPS][160];
    __shared__ __align__(16) float sC[SC_STAGES][SC_STEPS][160];
    __shared__ __align__(16) float sx[SC_STAGES][SC_STEPS][64];
    __shared__ float sdA[SC_STAGES][SC_STEPS];
    __shared__ float sdt[SC_STAGES][SC_STEPS];

    auto load_stage = [&](int slot, int l0) {
#pragma unroll
        for (int pass = 0; pass < 2; pass++) {
            const int idx = tid + pass * 256;
            if (idx < 320) {
                const int j = idx / 80, op = idx % 80;
                const float* row = xc + (size_t)(l0 + j) * CONVDIM;
                if (op < 64) {
                    const int isC = op >> 5, o = op & 31;
                    const int chunk = o >> 2, q = o & 3;
                    const float* src = row + DIN + isC * DSTATE + chunk * 16 + q * 4;
                    float* dstf = (isC ? &sC[slot][j][0] : &sB[slot][j][0]) + chunk * 20 + q * 4;
                    cp16(smem_u32(dstf), src, 16);
                } else {
                    const int o = op - 64;
                    cp16(smem_u32(&sx[slot][j][o * 4]), row + h * HD + o * 4, 16);
                }
            } else if (idx < 328) {
                const int t = idx - 320, j = t >> 1;
                if (t & 1) cp4(smem_u32(&sdt[slot][j]), dtp + (size_t)(l0 + j) * NH);
                else       cp4(smem_u32(&sdA[slot][j]), dAp + (size_t)(l0 + j) * NH);
            }
        }
    };

    ull hs0[8], hs1[8];
#pragma unroll
    for (int i = 0; i < 8; i++) { hs0[i] = 0ull; hs1[i] = 0ull; }
    const float Dh = Dv[h];

#pragma unroll
    for (int s = 0; s < SC_STAGES; s++) { load_stage(s, SC_STEPS * s); cp_commit(); }

    const int niter = LSEQ / SC_STEPS;
    for (int it = 0; it < niter; it++) {
        const int slot = it & (SC_STAGES - 1);
        cp_wait<SC_STAGES - 1>();
        __syncthreads();

        // register double-buffer for B/C/x/dA/dt
        ulonglong2 Bb[2][4], Cb[2][4];
        float2 xb[2];
        float dAb[2], dtb[2];
        {
            const ulonglong2* B2 = (const ulonglong2*)(&sB[slot][0][nc * 20]);
            const ulonglong2* C2 = (const ulonglong2*)(&sC[slot][0][nc * 20]);
#pragma unroll
            for (int i = 0; i < 4; i++) { Bb[0][i] = B2[i]; Cb[0][i] = C2[i]; }
            xb[0]  = *(const float2*)&sx[slot][0][p0];
            dAb[0] = sdA[slot][0];
            dtb[0] = sdt[slot][0];
        }

#pragma unroll
        for (int j = 0; j < SC_STEPS; j++) {
            const int cur = j & 1, nxt = cur ^ 1;
            if (j + 1 < SC_STEPS) {
                const ulonglong2* B2 = (const ulonglong2*)(&sB[slot][j + 1][nc * 20]);
                const ulonglong2* C2 = (const ulonglong2*)(&sC[slot][j + 1][nc * 20]);
#pragma unroll
                for (int i = 0; i < 4; i++) { Bb[nxt][i] = B2[i]; Cb[nxt][i] = C2[i]; }
                xb[nxt]  = *(const float2*)&sx[slot][j + 1][p0];
                dAb[nxt] = sdA[slot][j + 1];
                dtb[nxt] = sdt[slot][j + 1];
            }

            const float dAv = dAb[cur];
            const float dtv = dtb[cur];
            const float2 xv = xb[cur];
            const float s0 = dtv * xv.x, s1 = dtv * xv.y;
            const ull dA2 = pack2(dAv, dAv);
            const ull s20 = pack2(s0, s0);
            const ull s21 = pack2(s1, s1);

            ull acc0 = 0ull, acc1 = 0ull;
#pragma unroll
            for (int i = 0; i < 4; i++) {
                const ulonglong2 bb = Bb[cur][i], cc = Cb[cur][i];
                hs0[2*i]   = ffma2(dA2, hs0[2*i],   fmul2(s20, bb.x));
                acc0       = ffma2(hs0[2*i],   cc.x, acc0);
                hs1[2*i]   = ffma2(dA2, hs1[2*i],   fmul2(s21, bb.x));
                acc1       = ffma2(hs1[2*i],   cc.x, acc1);
                hs0[2*i+1] = ffma2(dA2, hs0[2*i+1], fmul2(s20, bb.y));
                acc0       = ffma2(hs0[2*i+1], cc.y, acc0);
                hs1[2*i+1] = ffma2(dA2, hs1[2*i+1], fmul2(s21, bb.y));
                acc1       = ffma2(hs1[2*i+1], cc.y, acc1);
            }
            const float2 f0 = unpack2(acc0), f1 = unpack2(acc1);
            float r0 = f0.x + f0.y;
            float r1 = f1.x + f1.y;
#pragma unroll
            for (int o = 1; o < 8; o <<= 1) {
                r0 += __shfl_xor_sync(0xffffffffu, r0, o);
                r1 += __shfl_xor_sync(0xffffffffu, r1, o);
            }
            if (nc == 0) {
                float2 ov;
                ov.x = r0 + Dh * xv.x;
                ov.y = r1 + Dh * xv.y;
                *(float2*)(yout + (size_t)(SC_STEPS * it + j) * DIN) = ov;
            }
        }
        __syncthreads();
        if (it + SC_STAGES < niter) load_stage(slot, SC_STEPS * (it + SC_STAGES));
        cp_commit();
    }
}

// ---------------- gating + RMSNorm -> fp16 ----------------
__global__ void __launch_bounds__(256)
gate_norm_kernel(const float* __restrict__ norm_w)
{
    const int bl = blockIdx.x;
    const float* yrow = g_y + (size_t)bl * DIN;
    const float* zrow = g_zxbcdt + (size_t)bl * DPROJ;
    __half* hrow = g_yh + (size_t)bl * DIN;
    const int tid = threadIdx.x;

    float v[8];
    float ss = 0.f;
#pragma unroll
    for (int j = 0; j < 8; j++) {
        const int c = tid + j * 256;
        const float z = zrow[c];
        const float val = yrow[c] * (z / (1.f + expf(-z)));
        v[j] = val;
        ss += val * val;
    }
#pragma unroll
    for (int o = 16; o; o >>= 1) ss += __shfl_xor_sync(0xffffffffu, ss, o);
    __shared__ float red[8];
    if ((tid & 31) == 0) red[tid >> 5] = ss;
    __syncthreads();
    float tot = 0.f;
#pragma unroll
    for (int i = 0; i < 8; i++) tot += red[i];
    const float scale = rsqrtf(tot * (1.f / (float)DIN) + 1e-5f);
#pragma unroll
    for (int j = 0; j < 8; j++) {
        const int c = tid + j * 256;
        hrow[c] = __float2half(v[j] * scale * norm_w[c]);
    }
}

// ---------------- launch ----------------
extern "C" void kernel_launch(void* const* d_in, const int* in_sizes, int n_in,
                              void* d_out, int out_size)
{
    (void)in_sizes; (void)n_in; (void)out_size;

    const float* hidden  = (const float*)d_in[0];
    const float* W_in    = (const float*)d_in[1];
    const float* conv_w  = (const float*)d_in[2];
    const float* conv_b  = (const float*)d_in[3];
    const float* dt_bias = (const float*)d_in[4];
    const float* A_log   = (const float*)d_in[5];
    const float* Dvec    = (const float*)d_in[6];
    const float* norm_w  = (const float*)d_in[7];
    const float* W_out   = (const float*)d_in[8];
    float* out = (float*)d_out;

    static float* zx = nullptr;
    static __half *ah, *w1h, *yh, *w2h;
    if (!zx) {
        void* p;
        cudaGetSymbolAddress(&p, g_zxbcdt); zx  = (float*)p;
        cudaGetSymbolAddress(&p, g_ah);   ah  = (__half*)p;
        cudaGetSymbolAddress(&p, g_w1h);  w1h = (__half*)p;
        cudaGetSymbolAddress(&p, g_yh);   yh  = (__half*)p;
        cudaGetSymbolAddress(&p, g_w2h);  w2h = (__half*)p;
        cudaFuncSetAttribute(gemm_hmma, cudaFuncAttributeMaxDynamicSharedMemorySize, GS_DYN);
    }

    // 0) operand prep (fp16)
    {
        const int n4 = MROWS * DMODEL / 4;
        convert_h<<<(n4 + 255) / 256, 256>>>(hidden, ah, n4);
    }
    transpose_h<<<dim3(DPROJ / 32, DMODEL / 32), 256>>>(W_in, w1h, DMODEL, DPROJ);
    transpose_h<<<dim3(DMODEL / 32, DIN / 32), 256>>>(W_out, w2h, DIN, DMODEL);

    // 1) zxbcdt = hidden @ W_in (fp16 HMMA, BK=64)
    gemm_hmma<<<dim3((DPROJ + 127) / 128, MROWS / 128), 256, GS_DYN>>>(
        ah, w1h, zx, DPROJ, DMODEL);

    // 2) conv + silu (8 steps/CTA) and dt/dA
    conv_kernel<<<MROWS / 8, 256>>>(conv_w, conv_b);
    dt_kernel<<<MROWS * NH / 256, 256>>>(dt_bias, A_log);

    // 3) selective scan (register double-buffered)
    scan_kernel<<<dim3(NH, BB), 256>>>(Dvec);

    // 4) gating + rmsnorm -> fp16
    gate_norm_kernel<<<MROWS, 256>>>(norm_w);

    // 5) out = y @ W_out
    gemm_hmma<<<dim3(DMODEL / 128, MROWS / 128), 256, GS_DYN>>>(
        yh, w2h, out, DMODEL, DIN);
}

// round 14
// speedup vs baseline: 1.1088x; 1.1088x over previous
#include <cuda_runtime.h>
#include <cuda_fp16.h>
#include <cuda_bf16.h>
#include <math.h>
#include <stdint.h>

// ---------------- problem constants ----------------
#define BB        4
#define LSEQ      2048
#define DMODEL    1024
#define DIN       2048          // D_INNER
#define NH        32            // NHEADS
#define HD        64            // HEADDIM
#define DSTATE    128
#define CONVDIM   2304          // DIN + 2*DSTATE
#define DPROJ     4384          // 2*DIN + 2*DSTATE + NH
#define MROWS     (BB*LSEQ)     // 8192

// SSD chunking
#define QC        64            // chunk length
#define NCHUNK    (LSEQ/QC)     // 32
#define NCID      (BB*NH*NCHUNK)// 4096
#define ST128     136           // smem stride (halfs) for 128-wide K rows
#define ST64      72            // smem stride (halfs) for 64-wide K rows

typedef unsigned long long ull;

// ---------------- scratch (static __device__, no allocs) ----------------
__device__ float g_zxbcdt[(size_t)MROWS * DPROJ];
__device__ float g_xc[(size_t)MROWS * CONVDIM];
__device__ float g_y[(size_t)MROWS * DIN];
__device__ float g_dt[(size_t)MROWS * NH];
__device__ float g_ldA[(size_t)MROWS * NH];          // log(dA) = -exp(A_log)*dt

// fp16 GEMM operands
__device__ __half g_ah[(size_t)MROWS * DMODEL];
__device__ __half g_w1h[(size_t)DPROJ * DMODEL];     // W_in^T  [N][K]
__device__ __half g_yh[(size_t)MROWS * DIN];
__device__ __half g_w2h[(size_t)DMODEL * DIN];       // W_out^T [N][K]

// SSD intermediates
__device__ float  gU[(size_t)NCID * HD * DSTATE];    // per-chunk state contribution (fp32)
__device__ __half ghp[(size_t)NCID * HD * DSTATE];   // h_prev per chunk [p][n] fp16
__device__ __half gCh[(size_t)MROWS * DSTATE];       // C rows fp16 (reused by K3)
__device__ float  gCT[NCID * QC];                    // exp(cl[t]) per chunk
__device__ float  gaQ[NCID];                         // exp(cl[Q-1]) per chunk

// ---------------- mma.sync / ldmatrix / cp.async helpers ----------------
__device__ __forceinline__ uint32_t smem_u32(const void* p) {
    uint32_t a;
    asm("{ .reg .u64 t; cvta.to.shared.u64 t, %1; cvt.u32.u64 %0, t; }" : "=r"(a) : "l"(p));
    return a;
}
__device__ __forceinline__ void ldsm4(uint32_t& r0, uint32_t& r1, uint32_t& r2, uint32_t& r3,
                                      uint32_t addr) {
    asm volatile("ldmatrix.sync.aligned.m8n8.x4.shared.b16 {%0,%1,%2,%3}, [%4];"
                 : "=r"(r0), "=r"(r1), "=r"(r2), "=r"(r3) : "r"(addr));
}
__device__ __forceinline__ void mma16816h(float* c, uint32_t a0, uint32_t a1, uint32_t a2,
                                          uint32_t a3, uint32_t b0, uint32_t b1) {
    asm volatile(
        "mma.sync.aligned.m16n8k16.row.col.f32.f16.f16.f32 "
        "{%0,%1,%2,%3}, {%4,%5,%6,%7}, {%8,%9}, {%0,%1,%2,%3};"
        : "+f"(c[0]), "+f"(c[1]), "+f"(c[2]), "+f"(c[3])
        : "r"(a0), "r"(a1), "r"(a2), "r"(a3), "r"(b0), "r"(b1));
}
__device__ __forceinline__ void cp16(uint32_t saddr, const void* gaddr, uint32_t srcbytes) {
    asm volatile("cp.async.cg.shared.global [%0], [%1], 16, %2;"
                 :: "r"(saddr), "l"(gaddr), "r"(srcbytes));
}
__device__ __forceinline__ void cp_commit() { asm volatile("cp.async.commit_group;"); }
template <int N_> __device__ __forceinline__ void cp_wait() {
    asm volatile("cp.async.wait_group %0;" :: "n"(N_));
}

// ---------------- converters (fp32 -> fp16) ----------------
__global__ void __launch_bounds__(256)
convert_h(const float* __restrict__ src, __half* __restrict__ dst, int n4)
{
    int i = blockIdx.x * 256 + threadIdx.x;
    if (i >= n4) return;
    float4 v = ((const float4*)src)[i];
    __half2 h0; h0.x = __float2half(v.x); h0.y = __float2half(v.y);
    __half2 h1; h1.x = __float2half(v.z); h1.y = __float2half(v.w);
    ((__half2*)dst)[i*2]   = h0;
    ((__half2*)dst)[i*2+1] = h1;
}

__global__ void __launch_bounds__(256)
transpose_h(const float* __restrict__ src, __half* __restrict__ dstT, int K, int N)
{
    __shared__ float t[32][33];
    const int kb = blockIdx.y * 32, nb = blockIdx.x * 32;
    const int tx = threadIdx.x & 31, ty = threadIdx.x >> 5;
#pragma unroll
    for (int j = 0; j < 4; j++)
        t[ty + j*8][tx] = src[(size_t)(kb + ty + j*8) * N + nb + tx];
    __syncthreads();
#pragma unroll
    for (int j = 0; j < 4; j++) {
        const int n = nb + ty + j*8, k = kb + tx;
        dstT[(size_t)n * K + k] = __float2half(t[tx][ty + j*8]);
    }
}

// ---------------- HMMA GEMM (frozen from R12 — 247us GEMM1) ------------------
#define GS_STRIDE 144
#define GS_TILE   (128 * GS_STRIDE)
#define GS_BUF    (2 * GS_TILE)
#define GS_DYN    (2 * GS_BUF)

__global__ void __launch_bounds__(256)
gemm_hmma(const __half* __restrict__ A, const __half* __restrict__ BT,
          float* __restrict__ C, int N, int K)
{
    extern __shared__ char smem[];
    const uint32_t sb = smem_u32(smem);

    const int tid = threadIdx.x;
    const int lane = tid & 31;
    const int wid = tid >> 5;
    const int warp_m = wid & 1;
    const int warp_n = wid >> 1;
    const int rowBase = blockIdx.y << 7;
    const int colBase = blockIdx.x << 7;
    const int nkc = K >> 6;

    float acc[4][4][4];
#pragma unroll
    for (int i = 0; i < 4; i++)
#pragma unroll
        for (int j = 0; j < 4; j++)
#pragma unroll
            for (int q = 0; q < 4; q++) acc[i][j][q] = 0.f;

    auto load_chunk = [&](int kc, int buf) {
        const uint32_t base = sb + (uint32_t)buf * GS_BUF;
#pragma unroll
        for (int it = 0; it < 4; it++) {
            const int id = tid + it * 256;
            const int row = id >> 3, c = id & 7;
            const size_t g = (size_t)(rowBase + row) * K + kc * 64 + c * 8;
            cp16(base + (uint32_t)(row * GS_STRIDE + c * 16), A + g, 16);
        }
#pragma unroll
        for (int it = 0; it < 4; it++) {
            const int id = tid + it * 256;
            const int row = id >> 3, c = id & 7;
            const int n = colBase + row;
            const int nn = (n < N) ? n : 0;
            const uint32_t valid = (n < N) ? 16u : 0u;
            const size_t g = (size_t)nn * K + kc * 64 + c * 8;
            cp16(base + GS_TILE + (uint32_t)(row * GS_STRIDE + c * 16), BT + g, valid);
        }
    };

    load_chunk(0, 0);
    cp_commit();

    for (int kc = 0; kc < nkc; kc++) {
        const int buf = kc & 1;
        if (kc + 1 < nkc) {
            load_chunk(kc + 1, buf ^ 1);
            cp_commit();
            cp_wait<1>();
        } else {
            cp_wait<0>();
        }
        __syncthreads();

        const uint32_t aTb = sb + (uint32_t)buf * GS_BUF;
        const uint32_t bTb = aTb + GS_TILE;

#pragma unroll
        for (int ks = 0; ks < 4; ks++) {
            const uint32_t loff = (uint32_t)((lane & 15) * GS_STRIDE + (lane >> 4) * 16 + ks * 32);

            uint32_t aH[4][4];
#pragma unroll
            for (int mt = 0; mt < 4; mt++) {
                const uint32_t ro = (uint32_t)((warp_m * 64 + mt * 16) * GS_STRIDE) + loff;
                ldsm4(aH[mt][0], aH[mt][1], aH[mt][2], aH[mt][3], aTb + ro);
            }
            uint32_t bH[4][2];
#pragma unroll
            for (int np = 0; np < 2; np++) {
                const uint32_t ro = (uint32_t)((warp_n * 32 + np * 16) * GS_STRIDE) + loff;
                uint32_t r0, r1, r2, r3;
                ldsm4(r0, r1, r2, r3, bTb + ro);
                bH[np*2][0] = r0; bH[np*2][1] = r2;
                bH[np*2+1][0] = r1; bH[np*2+1][1] = r3;
            }
#pragma unroll
            for (int mt = 0; mt < 4; mt++)
#pragma unroll
                for (int nt = 0; nt < 4; nt++)
                    mma16816h(acc[mt][nt], aH[mt][0], aH[mt][1], aH[mt][2], aH[mt][3],
                              bH[nt][0], bH[nt][1]);
        }
        __syncthreads();
    }

    const int g = lane >> 2, tg = lane & 3;
#pragma unroll
    for (int mt = 0; mt < 4; mt++) {
#pragma unroll
        for (int nt = 0; nt < 4; nt++) {
            const int col = colBase + warp_n * 32 + nt * 8 + tg * 2;
            if (col < N) {
                const int r0 = rowBase + warp_m * 64 + mt * 16 + g;
                float2 v0 = make_float2(acc[mt][nt][0], acc[mt][nt][1]);
                float2 v1 = make_float2(acc[mt][nt][2], acc[mt][nt][3]);
                *(float2*)(C + (size_t)r0 * N + col)       = v0;
                *(float2*)(C + (size_t)(r0 + 8) * N + col) = v1;
            }
        }
    }
}

// ---------------- conv(4) + SiLU (unchanged) ----------------
__global__ void __launch_bounds__(256)
conv_kernel(const float* __restrict__ conv_w, const float* __restrict__ conv_b)
{
    const int bl0 = blockIdx.x * 8;
    const int l0  = bl0 & (LSEQ - 1);
    const int tid = threadIdx.x;
    const float* base = g_zxbcdt + (size_t)bl0 * DPROJ + DIN;
    float* out = g_xc + (size_t)bl0 * CONVDIM;

    for (int c = tid; c < CONVDIM; c += 256) {
        const float4 w = *(const float4*)(conv_w + c * 4);
        const float bias = conv_b[c];
        float v[11];
#pragma unroll
        for (int k = 0; k < 11; k++) {
            const int ll = l0 + k - 3;
            v[k] = (ll >= 0) ? base[(ptrdiff_t)(k - 3) * DPROJ + c] : 0.f;
        }
#pragma unroll
        for (int j = 0; j < 8; j++) {
            const float a = bias + w.x * v[j] + w.y * v[j+1] + w.z * v[j+2] + w.w * v[j+3];
            out[(size_t)j * CONVDIM + c] = a / (1.f + expf(-a));
        }
    }
}

// ---------------- dt / log-dA ----------------
__global__ void __launch_bounds__(256)
dt_kernel(const float* __restrict__ dt_bias, const float* __restrict__ A_log)
{
    const int idx = blockIdx.x * 256 + threadIdx.x;
    const int bl = idx >> 5, hh = idx & 31;
    const float v = g_zxbcdt[(size_t)bl * DPROJ + (DPROJ - NH) + hh] + dt_bias[hh];
    const float dtv = (v > 20.f) ? v : log1pf(expf(v));
    g_dt[idx]  = dtv;
    g_ldA[idx] = -expf(A_log[hh]) * dtv;
}

// ---------------- SSD K1: per-chunk G/S/Y_intra/U ----------------
// grid (NCHUNK, NH, BB), 256 threads (8 warps: wm = wid&3 m-block, wn = wid>>2)
#define SSD1_SMEM ((2*QC*ST128 + 128*ST64 + 3*QC*ST64) * 2 + 3*QC*4)

__global__ void __launch_bounds__(256)
ssd_chunk_kernel(const float* __restrict__ Dv)
{
    extern __shared__ char dsm[];
    __half* sC   = (__half*)dsm;                 // [QC][ST128]  C (A-op for G)
    __half* sB   = sC   + QC * ST128;            // [QC][ST128]  B (B-op for G)
    __half* sBTu = sB   + QC * ST128;            // [128][ST64]  uw-scaled B^T (B-op for U)
    __half* sX   = sBTu + 128 * ST64;            // [QC][ST64]   x [s][p]
    __half* sXT  = sX   + QC * ST64;             // [QC][ST64]   x^T [p][s]
    __half* sS   = sXT  + QC * ST64;             // [QC][ST64]   masked scores
    float*  cl   = (float*)(sS + QC * ST64);     // cumlog
    float*  sdt  = cl  + QC;
    float*  suw  = sdt + QC;

    const int k = blockIdx.x, h = blockIdx.y, b = blockIdx.z;
    const int cid = (b * NH + h) * NCHUNK + k;
    const int l0 = b * LSEQ + k * QC;
    const int tid = threadIdx.x, lane = tid & 31, wid = tid >> 5;
    const int wm = wid & 3, wn = wid >> 2;
    const int g = lane >> 2, tg = lane & 3;

    // phase 0: dt, log-dA, cumulative log
    if (tid < QC) {
        sdt[tid] = g_dt[(size_t)(l0 + tid) * NH + h];
        cl[tid]  = g_ldA[(size_t)(l0 + tid) * NH + h];
    }
    __syncthreads();
    if (tid == 0) {
        float run = 0.f;
        for (int t = 0; t < QC; t++) { run += cl[t]; cl[t] = run; }
    }
    __syncthreads();
    if (tid < QC) {
        suw[tid] = __expf(cl[QC-1] - cl[tid]) * sdt[tid];
        gCT[cid * QC + tid] = __expf(cl[tid]);
        if (tid == 0) gaQ[cid] = __expf(cl[QC-1]);
    }
    __syncthreads();

    // phase 1: load + convert chunk operands
    const float* xcb = g_xc + (size_t)l0 * CONVDIM;
    for (int i = tid; i < QC * 128; i += 256) {
        const int s = i >> 7, n = i & 127;
        const float cv = xcb[(size_t)s * CONVDIM + DIN + DSTATE + n];
        const __half chh = __float2half(cv);
        sC[s * ST128 + n] = chh;
        gCh[(size_t)(l0 + s) * DSTATE + n] = chh;
        const float bv = xcb[(size_t)s * CONVDIM + DIN + n];
        sB[s * ST128 + n] = __float2half(bv);
        sBTu[n * ST64 + s] = __float2half(bv * suw[s]);
    }
    for (int i = tid; i < QC * QC; i += 256) {
        const int s = i >> 6, p = i & 63;
        const float xv = xcb[(size_t)s * CONVDIM + h * HD + p];
        sX[s * ST64 + p]  = __float2half(xv);
        sXT[p * ST64 + s] = __float2half(xv);
    }
    __syncthreads();

    const uint32_t sCb  = smem_u32(sC);
    const uint32_t sBb  = smem_u32(sB);
    const uint32_t sSb  = smem_u32(sS);
    const uint32_t sXTb = smem_u32(sXT);
    const uint32_t sBTb = smem_u32(sBTu);

    // ---- G = C @ B^T (M=t, N=s, K=n=128), mask -> sS ----
    {
        float acc[4][4];
#pragma unroll
        for (int j = 0; j < 4; j++)
#pragma unroll
            for (int q = 0; q < 4; q++) acc[j][q] = 0.f;
#pragma unroll
        for (int ks = 0; ks < 8; ks++) {
            uint32_t a0, a1, a2, a3;
            ldsm4(a0, a1, a2, a3,
                  sCb + (uint32_t)(((16*wm + (lane & 15)) * ST128 + ks*16 + (lane >> 4)*8) * 2));
            uint32_t bf[4][2];
#pragma unroll
            for (int j = 0; j < 2; j++) {
                uint32_t r0, r1, r2, r3;
                ldsm4(r0, r1, r2, r3,
                      sBb + (uint32_t)(((32*wn + 16*j + (lane & 15)) * ST128 + ks*16 + (lane >> 4)*8) * 2));
                bf[2*j][0] = r0; bf[2*j][1] = r2;
                bf[2*j+1][0] = r1; bf[2*j+1][1] = r3;
            }
#pragma unroll
            for (int j = 0; j < 4; j++)
                mma16816h(acc[j], a0, a1, a2, a3, bf[j][0], bf[j][1]);
        }
#pragma unroll
        for (int j = 0; j < 4; j++) {
            const int s0 = 32*wn + j*8 + tg*2;
#pragma unroll
            for (int q = 0; q < 4; q++) {
                const int t = 16*wm + g + ((q >> 1) << 3);
                const int s = s0 + (q & 1);
                float w = 0.f;
                if (s <= t) w = __expf(cl[t] - cl[s]) * sdt[s];
                sS[t * ST64 + s] = __float2half(acc[j][q] * w);
            }
        }
    }
    __syncthreads();

    // ---- Y_intra = S @ X^T (M=t, N=p, K=s=64) + D*x -> g_y ----
    {
        float acc[4][4];
#pragma unroll
        for (int j = 0; j < 4; j++)
#pragma unroll
            for (int q = 0; q < 4; q++) acc[j][q] = 0.f;
#pragma unroll
        for (int ks = 0; ks < 4; ks++) {
            uint32_t a0, a1, a2, a3;
            ldsm4(a0, a1, a2, a3,
                  sSb + (uint32_t)(((16*wm + (lane & 15)) * ST64 + ks*16 + (lane >> 4)*8) * 2));
            uint32_t bf[4][2];
#pragma unroll
            for (int j = 0; j < 2; j++) {
                uint32_t r0, r1, r2, r3;
                ldsm4(r0, r1, r2, r3,
                      sXTb + (uint32_t)(((32*wn + 16*j + (lane & 15)) * ST64 + ks*16 + (lane >> 4)*8) * 2));
                bf[2*j][0] = r0; bf[2*j][1] = r2;
                bf[2*j+1][0] = r1; bf[2*j+1][1] = r3;
            }
#pragma unroll
            for (int j = 0; j < 4; j++)
                mma16816h(acc[j], a0, a1, a2, a3, bf[j][0], bf[j][1]);
        }
        const float Dh = Dv[h];
#pragma unroll
        for (int j = 0; j < 4; j++) {
            const int p0 = 32*wn + j*8 + tg*2;
#pragma unroll
            for (int hf = 0; hf < 2; hf++) {
                const int t = 16*wm + g + hf*8;
                float2 v;
                v.x = acc[j][hf*2+0] + Dh * __half2float(sX[t * ST64 + p0]);
                v.y = acc[j][hf*2+1] + Dh * __half2float(sX[t * ST64 + p0 + 1]);
                *(float2*)(g_y + (size_t)(l0 + t) * DIN + h * HD + p0) = v;
            }
        }
    }

    // ---- U = X^T @ (uw*B)^T (M=p, N=n=128, K=s=64) -> gU ----
    {
        float acc[8][4];
#pragma unroll
        for (int j = 0; j < 8; j++)
#pragma unroll
            for (int q = 0; q < 4; q++) acc[j][q] = 0.f;
#pragma unroll
        for (int ks = 0; ks < 4; ks++) {
            uint32_t a0, a1, a2, a3;
            ldsm4(a0, a1, a2, a3,
                  sXTb + (uint32_t)(((16*wm + (lane & 15)) * ST64 + ks*16 + (lane >> 4)*8) * 2));
            uint32_t bf[8][2];
#pragma unroll
            for (int j = 0; j < 4; j++) {
                uint32_t r0, r1, r2, r3;
                ldsm4(r0, r1, r2, r3,
                      sBTb + (uint32_t)(((64*wn + 16*j + (lane & 15)) * ST64 + ks*16 + (lane >> 4)*8) * 2));
                bf[2*j][0] = r0; bf[2*j][1] = r2;
                bf[2*j+1][0] = r1; bf[2*j+1][1] = r3;
            }
#pragma unroll
            for (int j = 0; j < 8; j++)
                mma16816h(acc[j], a0, a1, a2, a3, bf[j][0], bf[j][1]);
        }
#pragma unroll
        for (int j = 0; j < 8; j++) {
            const int n0 = 64*wn + j*8 + tg*2;
#pragma unroll
            for (int hf = 0; hf < 2; hf++) {
                const int p = 16*wm + g + hf*8;
                float2 v = make_float2(acc[j][hf*2], acc[j][hf*2+1]);
                *(float2*)(gU + (size_t)cid * (HD*DSTATE) + p * DSTATE + n0) = v;
            }
        }
    }
}

// ---------------- SSD K2: sequential chunk-state recurrence ----------------
// grid (NH, BB), 256 thr: thread owns p = tid>>2, n block (tid&3)*32 (32 states)
__global__ void __launch_bounds__(256)
ssd_state_kernel()
{
    const int h = blockIdx.x, b = blockIdx.y;
    const int tid = threadIdx.x;
    const int p = tid >> 2, nq = (tid & 3) * 32;

    float hreg[32];
#pragma unroll
    for (int i = 0; i < 32; i++) hreg[i] = 0.f;

    for (int k = 0; k < NCHUNK; k++) {
        const int cid = (b * NH + h) * NCHUNK + k;
        const size_t off = (size_t)cid * (HD*DSTATE) + p * DSTATE + nq;
        __half2* hp2 = (__half2*)(ghp + off);
#pragma unroll
        for (int i = 0; i < 16; i++) {
            __half2 hv;
            hv.x = __float2half(hreg[2*i]);
            hv.y = __float2half(hreg[2*i+1]);
            hp2[i] = hv;
        }
        const float aq = gaQ[cid];
        const float4* u4 = (const float4*)(gU + off);
#pragma unroll
        for (int i = 0; i < 8; i++) {
            const float4 u = u4[i];
            hreg[4*i+0] = aq * hreg[4*i+0] + u.x;
            hreg[4*i+1] = aq * hreg[4*i+1] + u.y;
            hreg[4*i+2] = aq * hreg[4*i+2] + u.z;
            hreg[4*i+3] = aq * hreg[4*i+3] + u.w;
        }
    }
}

// ---------------- SSD K3: Y_inter = ct(t) * C @ h_prev^T, += g_y ------------
__global__ void __launch_bounds__(256)
ssd_inter_kernel()
{
    __shared__ __half sCc[QC * ST128];
    __shared__ __half sHp[QC * ST128];
    __shared__ float sct[QC];

    const int k = blockIdx.x, h = blockIdx.y, b = blockIdx.z;
    const int cid = (b * NH + h) * NCHUNK + k;
    const int l0 = b * LSEQ + k * QC;
    const int tid = threadIdx.x, lane = tid & 31, wid = tid >> 5;
    const int wm = wid & 3, wn = wid >> 2;
    const int g = lane >> 2, tg = lane & 3;

    for (int i = tid; i < QC * 128; i += 256) {
        const int s = i >> 7, n = i & 127;
        sCc[s * ST128 + n] = gCh[(size_t)(l0 + s) * DSTATE + n];
        sHp[s * ST128 + n] = ghp[(size_t)cid * (HD*DSTATE) + i];
    }
    if (tid < QC) sct[tid] = gCT[cid * QC + tid];
    __syncthreads();

    const uint32_t sCb = smem_u32(sCc);
    const uint32_t sHb = smem_u32(sHp);

    float acc[4][4];
#pragma unroll
    for (int j = 0; j < 4; j++)
#pragma unroll
        for (int q = 0; q < 4; q++) acc[j][q] = 0.f;
#pragma unroll
    for (int ks = 0; ks < 8; ks++) {
        uint32_t a0, a1, a2, a3;
        ldsm4(a0, a1, a2, a3,
              sCb + (uint32_t)(((16*wm + (lane & 15)) * ST128 + ks*16 + (lane >> 4)*8) * 2));
        uint32_t bf[4][2];
#pragma unroll
        for (int j = 0; j < 2; j++) {
            uint32_t r0, r1, r2, r3;
            ldsm4(r0, r1, r2, r3,
                  sHb + (uint32_t)(((32*wn + 16*j + (lane & 15)) * ST128 + ks*16 + (lane >> 4)*8) * 2));
            bf[2*j][0] = r0; bf[2*j][1] = r2;
            bf[2*j+1][0] = r1; bf[2*j+1][1] = r3;
        }
#pragma unroll
        for (int j = 0; j < 4; j++)
            mma16816h(acc[j], a0, a1, a2, a3, bf[j][0], bf[j][1]);
    }
#pragma unroll
    for (int j = 0; j < 4; j++) {
        const int p0 = 32*wn + j*8 + tg*2;
#pragma unroll
        for (int hf = 0; hf < 2; hf++) {
            const int t = 16*wm + g + hf*8;
            const float ct = sct[t];
            float2* yp = (float2*)(g_y + (size_t)(l0 + t) * DIN + h * HD + p0);
            float2 v = *yp;
            v.x += acc[j][hf*2]   * ct;
            v.y += acc[j][hf*2+1] * ct;
            *yp = v;
        }
    }
}

// ---------------- gating + RMSNorm -> fp16 ----------------
__global__ void __launch_bounds__(256)
gate_norm_kernel(const float* __restrict__ norm_w)
{
    const int bl = blockIdx.x;
    const float* yrow = g_y + (size_t)bl * DIN;
    const float* zrow = g_zxbcdt + (size_t)bl * DPROJ;
    __half* hrow = g_yh + (size_t)bl * DIN;
    const int tid = threadIdx.x;

    float v[8];
    float ss = 0.f;
#pragma unroll
    for (int j = 0; j < 8; j++) {
        const int c = tid + j * 256;
        const float z = zrow[c];
        const float val = yrow[c] * (z / (1.f + expf(-z)));
        v[j] = val;
        ss += val * val;
    }
#pragma unroll
    for (int o = 16; o; o >>= 1) ss += __shfl_xor_sync(0xffffffffu, ss, o);
    __shared__ float red[8];
    if ((tid & 31) == 0) red[tid >> 5] = ss;
    __syncthreads();
    float tot = 0.f;
#pragma unroll
    for (int i = 0; i < 8; i++) tot += red[i];
    const float scale = rsqrtf(tot * (1.f / (float)DIN) + 1e-5f);
#pragma unroll
    for (int j = 0; j < 8; j++) {
        const int c = tid + j * 256;
        hrow[c] = __float2half(v[j] * scale * norm_w[c]);
    }
}

// ---------------- launch ----------------
extern "C" void kernel_launch(void* const* d_in, const int* in_sizes, int n_in,
                              void* d_out, int out_size)
{
    (void)in_sizes; (void)n_in; (void)out_size;

    const float* hidden  = (const float*)d_in[0];
    const float* W_in    = (const float*)d_in[1];
    const float* conv_w  = (const float*)d_in[2];
    const float* conv_b  = (const float*)d_in[3];
    const float* dt_bias = (const float*)d_in[4];
    const float* A_log   = (const float*)d_in[5];
    const float* Dvec    = (const float*)d_in[6];
    const float* norm_w  = (const float*)d_in[7];
    const float* W_out   = (const float*)d_in[8];
    float* out = (float*)d_out;

    static float* zx = nullptr;
    static __half *ah, *w1h, *yh, *w2h;
    if (!zx) {
        void* p;
        cudaGetSymbolAddress(&p, g_zxbcdt); zx  = (float*)p;
        cudaGetSymbolAddress(&p, g_ah);   ah  = (__half*)p;
        cudaGetSymbolAddress(&p, g_w1h);  w1h = (__half*)p;
        cudaGetSymbolAddress(&p, g_yh);   yh  = (__half*)p;
        cudaGetSymbolAddress(&p, g_w2h);  w2h = (__half*)p;
        cudaFuncSetAttribute(gemm_hmma, cudaFuncAttributeMaxDynamicSharedMemorySize, GS_DYN);
        cudaFuncSetAttribute(ssd_chunk_kernel, cudaFuncAttributeMaxDynamicSharedMemorySize, SSD1_SMEM);
    }

    // 0) operand prep (fp16)
    {
        const int n4 = MROWS * DMODEL / 4;
        convert_h<<<(n4 + 255) / 256, 256>>>(hidden, ah, n4);
    }
    transpose_h<<<dim3(DPROJ / 32, DMODEL / 32), 256>>>(W_in, w1h, DMODEL, DPROJ);
    transpose_h<<<dim3(DMODEL / 32, DIN / 32), 256>>>(W_out, w2h, DIN, DMODEL);

    // 1) zxbcdt = hidden @ W_in
    gemm_hmma<<<dim3((DPROJ + 127) / 128, MROWS / 128), 256, GS_DYN>>>(
        ah, w1h, zx, DPROJ, DMODEL);

    // 2) conv + silu, dt/ldA
    conv_kernel<<<MROWS / 8, 256>>>(conv_w, conv_b);
    dt_kernel<<<MROWS * NH / 256, 256>>>(dt_bias, A_log);

    // 3) SSD: intra-chunk (tensor cores) -> state recurrence -> inter-chunk
    ssd_chunk_kernel<<<dim3(NCHUNK, NH, BB), 256, SSD1_SMEM>>>(Dvec);
    ssd_state_kernel<<<dim3(NH, BB), 256>>>();
    ssd_inter_kernel<<<dim3(NCHUNK, NH, BB), 256>>>();

    // 4) gating + rmsnorm -> fp16
    gate_norm_kernel<<<MROWS, 256>>>(norm_w);

    // 5) out = y @ W_out
    gemm_hmma<<<dim3(DMODEL / 128, MROWS / 128), 256, GS_DYN>>>(
        yh, w2h, out, DMODEL, DIN);
}

// round 17
// speedup vs baseline: 1.1295x; 1.0186x over previous
#include <cuda_runtime.h>
#include <cuda_fp16.h>
#include <cuda_bf16.h>
#include <math.h>
#include <stdint.h>

// ---------------- problem constants ----------------
#define BB        4
#define LSEQ      2048
#define DMODEL    1024
#define DIN       2048          // D_INNER
#define NH        32            // NHEADS
#define HD        64            // HEADDIM
#define DSTATE    128
#define CONVDIM   2304          // DIN + 2*DSTATE
#define DPROJ     4384          // 2*DIN + 2*DSTATE + NH
#define MROWS     (BB*LSEQ)     // 8192

// SSD chunking
#define QC        64
#define NCHUNK    (LSEQ/QC)     // 32
#define NCID      (BB*NH*NCHUNK)// 4096
#define ST128     136
#define ST64      72

typedef unsigned long long ull;

// ---------------- scratch (static __device__, no allocs) ----------------
__device__ float g_zxbcdt[(size_t)MROWS * DPROJ];
__device__ float g_xc[(size_t)MROWS * CONVDIM];
__device__ float g_y[(size_t)MROWS * DIN];
__device__ float g_dt[(size_t)MROWS * NH];
__device__ float g_ldA[(size_t)MROWS * NH];

// fp16 GEMM operands
__device__ __half g_ah[(size_t)MROWS * DMODEL];
__device__ __half g_w1h[(size_t)DPROJ * DMODEL];
__device__ __half g_yh[(size_t)MROWS * DIN];
__device__ __half g_w2h[(size_t)DMODEL * DIN];

// SSD intermediates
__device__ float  gU[(size_t)NCID * HD * DSTATE];
__device__ __half ghp[(size_t)NCID * HD * DSTATE];
__device__ __half gCh[(size_t)MROWS * DSTATE];
__device__ float  gCT[NCID * QC];
__device__ float  gaQ[NCID];

// ---------------- mma.sync / ldmatrix / cp.async helpers ----------------
__device__ __forceinline__ uint32_t smem_u32(const void* p) {
    uint32_t a;
    asm("{ .reg .u64 t; cvta.to.shared.u64 t, %1; cvt.u32.u64 %0, t; }" : "=r"(a) : "l"(p));
    return a;
}
__device__ __forceinline__ void ldsm4(uint32_t& r0, uint32_t& r1, uint32_t& r2, uint32_t& r3,
                                      uint32_t addr) {
    asm volatile("ldmatrix.sync.aligned.m8n8.x4.shared.b16 {%0,%1,%2,%3}, [%4];"
                 : "=r"(r0), "=r"(r1), "=r"(r2), "=r"(r3) : "r"(addr));
}
__device__ __forceinline__ void mma16816h(float* c, uint32_t a0, uint32_t a1, uint32_t a2,
                                          uint32_t a3, uint32_t b0, uint32_t b1) {
    asm volatile(
        "mma.sync.aligned.m16n8k16.row.col.f32.f16.f16.f32 "
        "{%0,%1,%2,%3}, {%4,%5,%6,%7}, {%8,%9}, {%0,%1,%2,%3};"
        : "+f"(c[0]), "+f"(c[1]), "+f"(c[2]), "+f"(c[3])
        : "r"(a0), "r"(a1), "r"(a2), "r"(a3), "r"(b0), "r"(b1));
}
__device__ __forceinline__ void cp16(uint32_t saddr, const void* gaddr, uint32_t srcbytes) {
    asm volatile("cp.async.cg.shared.global [%0], [%1], 16, %2;"
                 :: "r"(saddr), "l"(gaddr), "r"(srcbytes));
}
__device__ __forceinline__ void cp_commit() { asm volatile("cp.async.commit_group;"); }
template <int N_> __device__ __forceinline__ void cp_wait() {
    asm volatile("cp.async.wait_group %0;" :: "n"(N_));
}

// ---------------- converters (fp32 -> fp16) ----------------
__global__ void __launch_bounds__(256)
convert_h(const float* __restrict__ src, __half* __restrict__ dst, int n4)
{
    int i = blockIdx.x * 256 + threadIdx.x;
    if (i >= n4) return;
    float4 v = ((const float4*)src)[i];
    __half2 h0; h0.x = __float2half(v.x); h0.y = __float2half(v.y);
    __half2 h1; h1.x = __float2half(v.z); h1.y = __float2half(v.w);
    ((__half2*)dst)[i*2]   = h0;
    ((__half2*)dst)[i*2+1] = h1;
}

__global__ void __launch_bounds__(256)
transpose_h(const float* __restrict__ src, __half* __restrict__ dstT, int K, int N)
{
    __shared__ float t[32][33];
    const int kb = blockIdx.y * 32, nb = blockIdx.x * 32;
    const int tx = threadIdx.x & 31, ty = threadIdx.x >> 5;
#pragma unroll
    for (int j = 0; j < 4; j++)
        t[ty + j*8][tx] = src[(size_t)(kb + ty + j*8) * N + nb + tx];
    __syncthreads();
#pragma unroll
    for (int j = 0; j < 4; j++) {
        const int n = nb + ty + j*8, k = kb + tx;
        dstT[(size_t)n * K + k] = __float2half(t[tx][ty + j*8]);
    }
}

// ---------------- HMMA GEMM: BK=64, NOW 3-stage cp.async ---------------------
// Compute phase identical to R12's measured version; only pipeline depth changed.
#define GS_STRIDE 144
#define GS_TILE   (128 * GS_STRIDE)
#define GS_BUF    (2 * GS_TILE)       // 36864 B
#define GS_DYN    (3 * GS_BUF)        // 110592 B

__global__ void __launch_bounds__(256)
gemm_hmma(const __half* __restrict__ A, const __half* __restrict__ BT,
          float* __restrict__ C, int N, int K)
{
    extern __shared__ char smem[];
    const uint32_t sb = smem_u32(smem);

    const int tid = threadIdx.x;
    const int lane = tid & 31;
    const int wid = tid >> 5;
    const int warp_m = wid & 1;
    const int warp_n = wid >> 1;
    const int rowBase = blockIdx.y << 7;
    const int colBase = blockIdx.x << 7;
    const int nkc = K >> 6;

    float acc[4][4][4];
#pragma unroll
    for (int i = 0; i < 4; i++)
#pragma unroll
        for (int j = 0; j < 4; j++)
#pragma unroll
            for (int q = 0; q < 4; q++) acc[i][j][q] = 0.f;

    auto load_chunk = [&](int kc, int buf) {
        const uint32_t base = sb + (uint32_t)buf * GS_BUF;
#pragma unroll
        for (int it = 0; it < 4; it++) {
            const int id = tid + it * 256;
            const int row = id >> 3, c = id & 7;
            const size_t g = (size_t)(rowBase + row) * K + kc * 64 + c * 8;
            cp16(base + (uint32_t)(row * GS_STRIDE + c * 16), A + g, 16);
        }
#pragma unroll
        for (int it = 0; it < 4; it++) {
            const int id = tid + it * 256;
            const int row = id >> 3, c = id & 7;
            const int n = colBase + row;
            const int nn = (n < N) ? n : 0;
            const uint32_t valid = (n < N) ? 16u : 0u;
            const size_t g = (size_t)nn * K + kc * 64 + c * 8;
            cp16(base + GS_TILE + (uint32_t)(row * GS_STRIDE + c * 16), BT + g, valid);
        }
    };

    load_chunk(0, 0); cp_commit();
    load_chunk(1, 1); cp_commit();

    int slot = 0;
    for (int kc = 0; kc < nkc; kc++) {
        if (kc + 2 < nkc) load_chunk(kc + 2, (slot + 2) % 3);
        cp_commit();                 // unconditional: keeps group count aligned at tail
        cp_wait<2>();
        __syncthreads();

        const uint32_t aTb = sb + (uint32_t)slot * GS_BUF;
        const uint32_t bTb = aTb + GS_TILE;

#pragma unroll
        for (int ks = 0; ks < 4; ks++) {
            const uint32_t loff = (uint32_t)((lane & 15) * GS_STRIDE + (lane >> 4) * 16 + ks * 32);

            uint32_t aH[4][4];
#pragma unroll
            for (int mt = 0; mt < 4; mt++) {
                const uint32_t ro = (uint32_t)((warp_m * 64 + mt * 16) * GS_STRIDE) + loff;
                ldsm4(aH[mt][0], aH[mt][1], aH[mt][2], aH[mt][3], aTb + ro);
            }
            uint32_t bH[4][2];
#pragma unroll
            for (int np = 0; np < 2; np++) {
                const uint32_t ro = (uint32_t)((warp_n * 32 + np * 16) * GS_STRIDE) + loff;
                uint32_t r0, r1, r2, r3;
                ldsm4(r0, r1, r2, r3, bTb + ro);
                bH[np*2][0] = r0; bH[np*2][1] = r2;
                bH[np*2+1][0] = r1; bH[np*2+1][1] = r3;
            }
#pragma unroll
            for (int mt = 0; mt < 4; mt++)
#pragma unroll
                for (int nt = 0; nt < 4; nt++)
                    mma16816h(acc[mt][nt], aH[mt][0], aH[mt][1], aH[mt][2], aH[mt][3],
                              bH[nt][0], bH[nt][1]);
        }
        __syncthreads();
        slot = (slot + 1) % 3;
    }

    const int g = lane >> 2, tg = lane & 3;
#pragma unroll
    for (int mt = 0; mt < 4; mt++) {
#pragma unroll
        for (int nt = 0; nt < 4; nt++) {
            const int col = colBase + warp_n * 32 + nt * 8 + tg * 2;
            if (col < N) {
                const int r0 = rowBase + warp_m * 64 + mt * 16 + g;
                float2 v0 = make_float2(acc[mt][nt][0], acc[mt][nt][1]);
                float2 v1 = make_float2(acc[mt][nt][2], acc[mt][nt][3]);
                *(float2*)(C + (size_t)r0 * N + col)       = v0;
                *(float2*)(C + (size_t)(r0 + 8) * N + col) = v1;
            }
        }
    }
}

// ---------------- conv(4) + SiLU (unchanged) ----------------
__global__ void __launch_bounds__(256)
conv_kernel(const float* __restrict__ conv_w, const float* __restrict__ conv_b)
{
    const int bl0 = blockIdx.x * 8;
    const int l0  = bl0 & (LSEQ - 1);
    const int tid = threadIdx.x;
    const float* base = g_zxbcdt + (size_t)bl0 * DPROJ + DIN;
    float* out = g_xc + (size_t)bl0 * CONVDIM;

    for (int c = tid; c < CONVDIM; c += 256) {
        const float4 w = *(const float4*)(conv_w + c * 4);
        const float bias = conv_b[c];
        float v[11];
#pragma unroll
        for (int k = 0; k < 11; k++) {
            const int ll = l0 + k - 3;
            v[k] = (ll >= 0) ? base[(ptrdiff_t)(k - 3) * DPROJ + c] : 0.f;
        }
#pragma unroll
        for (int j = 0; j < 8; j++) {
            const float a = bias + w.x * v[j] + w.y * v[j+1] + w.z * v[j+2] + w.w * v[j+3];
            out[(size_t)j * CONVDIM + c] = a / (1.f + expf(-a));
        }
    }
}

// ---------------- dt / log-dA ----------------
__global__ void __launch_bounds__(256)
dt_kernel(const float* __restrict__ dt_bias, const float* __restrict__ A_log)
{
    const int idx = blockIdx.x * 256 + threadIdx.x;
    const int bl = idx >> 5, hh = idx & 31;
    const float v = g_zxbcdt[(size_t)bl * DPROJ + (DPROJ - NH) + hh] + dt_bias[hh];
    const float dtv = (v > 20.f) ? v : log1pf(expf(v));
    g_dt[idx]  = dtv;
    g_ldA[idx] = -expf(A_log[hh]) * dtv;
}

// ---------------- SSD K1: per-chunk G/S/Y_intra/U ----------------
#define SSD1_SMEM ((2*QC*ST128 + 128*ST64 + 3*QC*ST64) * 2 + 3*QC*4)

__global__ void __launch_bounds__(256)
ssd_chunk_kernel(const float* __restrict__ Dv)
{
    extern __shared__ char dsm[];
    __half* sC   = (__half*)dsm;
    __half* sB   = sC   + QC * ST128;
    __half* sBTu = sB   + QC * ST128;
    __half* sX   = sBTu + 128 * ST64;
    __half* sXT  = sX   + QC * ST64;
    __half* sS   = sXT  + QC * ST64;
    float*  cl   = (float*)(sS + QC * ST64);
    float*  sdt  = cl  + QC;
    float*  suw  = sdt + QC;

    const int k = blockIdx.x, h = blockIdx.y, b = blockIdx.z;
    const int cid = (b * NH + h) * NCHUNK + k;
    const int l0 = b * LSEQ + k * QC;
    const int tid = threadIdx.x, lane = tid & 31, wid = tid >> 5;
    const int wm = wid & 3, wn = wid >> 2;
    const int g = lane >> 2, tg = lane & 3;

    // phase 0: dt, log-dA, PARALLEL inclusive cumsum (Hillis-Steele)
    if (tid < QC) {
        sdt[tid] = g_dt[(size_t)(l0 + tid) * NH + h];
        cl[tid]  = g_ldA[(size_t)(l0 + tid) * NH + h];
    }
    __syncthreads();
#pragma unroll
    for (int d = 1; d < QC; d <<= 1) {
        float tv = 0.f;
        if (tid < QC && tid >= d) tv = cl[tid - d];
        __syncthreads();
        if (tid < QC) cl[tid] += tv;
        __syncthreads();
    }
    if (tid < QC) {
        suw[tid] = __expf(cl[QC-1] - cl[tid]) * sdt[tid];
        gCT[cid * QC + tid] = __expf(cl[tid]);
        if (tid == 0) gaQ[cid] = __expf(cl[QC-1]);
    }
    __syncthreads();

    // phase 1: load + convert chunk operands
    const float* xcb = g_xc + (size_t)l0 * CONVDIM;
    for (int i = tid; i < QC * 128; i += 256) {
        const int s = i >> 7, n = i & 127;
        const float cv = xcb[(size_t)s * CONVDIM + DIN + DSTATE + n];
        const __half chh = __float2half(cv);
        sC[s * ST128 + n] = chh;
        gCh[(size_t)(l0 + s) * DSTATE + n] = chh;
        const float bv = xcb[(size_t)s * CONVDIM + DIN + n];
        sB[s * ST128 + n] = __float2half(bv);
        sBTu[n * ST64 + s] = __float2half(bv * suw[s]);
    }
    for (int i = tid; i < QC * QC; i += 256) {
        const int s = i >> 6, p = i & 63;
        const float xv = xcb[(size_t)s * CONVDIM + h * HD + p];
        sX[s * ST64 + p]  = __float2half(xv);
        sXT[p * ST64 + s] = __float2half(xv);
    }
    __syncthreads();

    const uint32_t sCb  = smem_u32(sC);
    const uint32_t sBb  = smem_u32(sB);
    const uint32_t sSb  = smem_u32(sS);
    const uint32_t sXTb = smem_u32(sXT);
    const uint32_t sBTb = smem_u32(sBTu);

    // ---- G = C @ B^T, mask -> sS ----
    {
        float acc[4][4];
#pragma unroll
        for (int j = 0; j < 4; j++)
#pragma unroll
            for (int q = 0; q < 4; q++) acc[j][q] = 0.f;
#pragma unroll
        for (int ks = 0; ks < 8; ks++) {
            uint32_t a0, a1, a2, a3;
            ldsm4(a0, a1, a2, a3,
                  sCb + (uint32_t)(((16*wm + (lane & 15)) * ST128 + ks*16 + (lane >> 4)*8) * 2));
            uint32_t bf[4][2];
#pragma unroll
            for (int j = 0; j < 2; j++) {
                uint32_t r0, r1, r2, r3;
                ldsm4(r0, r1, r2, r3,
                      sBb + (uint32_t)(((32*wn + 16*j + (lane & 15)) * ST128 + ks*16 + (lane >> 4)*8) * 2));
                bf[2*j][0] = r0; bf[2*j][1] = r2;
                bf[2*j+1][0] = r1; bf[2*j+1][1] = r3;
            }
#pragma unroll
            for (int j = 0; j < 4; j++)
                mma16816h(acc[j], a0, a1, a2, a3, bf[j][0], bf[j][1]);
        }
#pragma unroll
        for (int j = 0; j < 4; j++) {
            const int s0 = 32*wn + j*8 + tg*2;
#pragma unroll
            for (int q = 0; q < 4; q++) {
                const int t = 16*wm + g + ((q >> 1) << 3);
                const int s = s0 + (q & 1);
                float w = 0.f;
                if (s <= t) w = __expf(cl[t] - cl[s]) * sdt[s];
                sS[t * ST64 + s] = __float2half(acc[j][q] * w);
            }
        }
    }
    __syncthreads();

    // ---- Y_intra = S @ X^T + D*x -> g_y ----
    {
        float acc[4][4];
#pragma unroll
        for (int j = 0; j < 4; j++)
#pragma unroll
            for (int q = 0; q < 4; q++) acc[j][q] = 0.f;
#pragma unroll
        for (int ks = 0; ks < 4; ks++) {
            uint32_t a0, a1, a2, a3;
            ldsm4(a0, a1, a2, a3,
                  sSb + (uint32_t)(((16*wm + (lane & 15)) * ST64 + ks*16 + (lane >> 4)*8) * 2));
            uint32_t bf[4][2];
#pragma unroll
            for (int j = 0; j < 2; j++) {
                uint32_t r0, r1, r2, r3;
                ldsm4(r0, r1, r2, r3,
                      sXTb + (uint32_t)(((32*wn + 16*j + (lane & 15)) * ST64 + ks*16 + (lane >> 4)*8) * 2));
                bf[2*j][0] = r0; bf[2*j][1] = r2;
                bf[2*j+1][0] = r1; bf[2*j+1][1] = r3;
            }
#pragma unroll
            for (int j = 0; j < 4; j++)
                mma16816h(acc[j], a0, a1, a2, a3, bf[j][0], bf[j][1]);
        }
        const float Dh = Dv[h];
#pragma unroll
        for (int j = 0; j < 4; j++) {
            const int p0 = 32*wn + j*8 + tg*2;
#pragma unroll
            for (int hf = 0; hf < 2; hf++) {
                const int t = 16*wm + g + hf*8;
                float2 v;
                v.x = acc[j][hf*2+0] + Dh * __half2float(sX[t * ST64 + p0]);
                v.y = acc[j][hf*2+1] + Dh * __half2float(sX[t * ST64 + p0 + 1]);
                *(float2*)(g_y + (size_t)(l0 + t) * DIN + h * HD + p0) = v;
            }
        }
    }

    // ---- U = X^T @ (uw*B)^T -> gU ----
    {
        float acc[8][4];
#pragma unroll
        for (int j = 0; j < 8; j++)
#pragma unroll
            for (int q = 0; q < 4; q++) acc[j][q] = 0.f;
#pragma unroll
        for (int ks = 0; ks < 4; ks++) {
            uint32_t a0, a1, a2, a3;
            ldsm4(a0, a1, a2, a3,
                  sXTb + (uint32_t)(((16*wm + (lane & 15)) * ST64 + ks*16 + (lane >> 4)*8) * 2));
            uint32_t bf[8][2];
#pragma unroll
            for (int j = 0; j < 4; j++) {
                uint32_t r0, r1, r2, r3;
                ldsm4(r0, r1, r2, r3,
                      sBTb + (uint32_t)(((64*wn + 16*j + (lane & 15)) * ST64 + ks*16 + (lane >> 4)*8) * 2));
                bf[2*j][0] = r0; bf[2*j][1] = r2;
                bf[2*j+1][0] = r1; bf[2*j+1][1] = r3;
            }
#pragma unroll
            for (int j = 0; j < 8; j++)
                mma16816h(acc[j], a0, a1, a2, a3, bf[j][0], bf[j][1]);
        }
#pragma unroll
        for (int j = 0; j < 8; j++) {
            const int n0 = 64*wn + j*8 + tg*2;
#pragma unroll
            for (int hf = 0; hf < 2; hf++) {
                const int p = 16*wm + g + hf*8;
                float2 v = make_float2(acc[j][hf*2], acc[j][hf*2+1]);
                *(float2*)(gU + (size_t)cid * (HD*DSTATE) + p * DSTATE + n0) = v;
            }
        }
    }
}

// ---------------- SSD K2: sequential chunk-state recurrence ----------------
__global__ void __launch_bounds__(256)
ssd_state_kernel()
{
    const int h = blockIdx.x, b = blockIdx.y;
    const int tid = threadIdx.x;
    const int p = tid >> 2, nq = (tid & 3) * 32;

    float hreg[32];
#pragma unroll
    for (int i = 0; i < 32; i++) hreg[i] = 0.f;

    for (int k = 0; k < NCHUNK; k++) {
        const int cid = (b * NH + h) * NCHUNK + k;
        const size_t off = (size_t)cid * (HD*DSTATE) + p * DSTATE + nq;
        __half2* hp2 = (__half2*)(ghp + off);
#pragma unroll
        for (int i = 0; i < 16; i++) {
            __half2 hv;
            hv.x = __float2half(hreg[2*i]);
            hv.y = __float2half(hreg[2*i+1]);
            hp2[i] = hv;
        }
        const float aq = gaQ[cid];
        const float4* u4 = (const float4*)(gU + off);
#pragma unroll
        for (int i = 0; i < 8; i++) {
            const float4 u = u4[i];
            hreg[4*i+0] = aq * hreg[4*i+0] + u.x;
            hreg[4*i+1] = aq * hreg[4*i+1] + u.y;
            hreg[4*i+2] = aq * hreg[4*i+2] + u.z;
            hreg[4*i+3] = aq * hreg[4*i+3] + u.w;
        }
    }
}

// ---------------- SSD K3: Y_inter = ct(t) * C @ h_prev^T, += g_y ------------
__global__ void __launch_bounds__(256)
ssd_inter_kernel()
{
    __shared__ __half sCc[QC * ST128];
    __shared__ __half sHp[QC * ST128];
    __shared__ float sct[QC];

    const int k = blockIdx.x, h = blockIdx.y, b = blockIdx.z;
    const int cid = (b * NH + h) * NCHUNK + k;
    const int l0 = b * LSEQ + k * QC;
    const int tid = threadIdx.x, lane = tid & 31, wid = tid >> 5;
    const int wm = wid & 3, wn = wid >> 2;
    const int g = lane >> 2, tg = lane & 3;

    for (int i = tid; i < QC * 128; i += 256) {
        const int s = i >> 7, n = i & 127;
        sCc[s * ST128 + n] = gCh[(size_t)(l0 + s) * DSTATE + n];
        sHp[s * ST128 + n] = ghp[(size_t)cid * (HD*DSTATE) + i];
    }
    if (tid < QC) sct[tid] = gCT[cid * QC + tid];
    __syncthreads();

    const uint32_t sCb = smem_u32(sCc);
    const uint32_t sHb = smem_u32(sHp);

    float acc[4][4];
#pragma unroll
    for (int j = 0; j < 4; j++)
#pragma unroll
        for (int q = 0; q < 4; q++) acc[j][q] = 0.f;
#pragma unroll
    for (int ks = 0; ks < 8; ks++) {
        uint32_t a0, a1, a2, a3;
        ldsm4(a0, a1, a2, a3,
              sCb + (uint32_t)(((16*wm + (lane & 15)) * ST128 + ks*16 + (lane >> 4)*8) * 2));
        uint32_t bf[4][2];
#pragma unroll
        for (int j = 0; j < 2; j++) {
            uint32_t r0, r1, r2, r3;
            ldsm4(r0, r1, r2, r3,
                  sHb + (uint32_t)(((32*wn + 16*j + (lane & 15)) * ST128 + ks*16 + (lane >> 4)*8) * 2));
            bf[2*j][0] = r0; bf[2*j][1] = r2;
            bf[2*j+1][0] = r1; bf[2*j+1][1] = r3;
        }
#pragma unroll
        for (int j = 0; j < 4; j++)
            mma16816h(acc[j], a0, a1, a2, a3, bf[j][0], bf[j][1]);
    }
#pragma unroll
    for (int j = 0; j < 4; j++) {
        const int p0 = 32*wn + j*8 + tg*2;
#pragma unroll
        for (int hf = 0; hf < 2; hf++) {
            const int t = 16*wm + g + hf*8;
            const float ct = sct[t];
            float2* yp = (float2*)(g_y + (size_t)(l0 + t) * DIN + h * HD + p0);
            float2 v = *yp;
            v.x += acc[j][hf*2]   * ct;
            v.y += acc[j][hf*2+1] * ct;
            *yp = v;
        }
    }
}

// ---------------- gating + RMSNorm -> fp16 ----------------
__global__ void __launch_bounds__(256)
gate_norm_kernel(const float* __restrict__ norm_w)
{
    const int bl = blockIdx.x;
    const float* yrow = g_y + (size_t)bl * DIN;
    const float* zrow = g_zxbcdt + (size_t)bl * DPROJ;
    __half* hrow = g_yh + (size_t)bl * DIN;
    const int tid = threadIdx.x;

    float v[8];
    float ss = 0.f;
#pragma unroll
    for (int j = 0; j < 8; j++) {
        const int c = tid + j * 256;
        const float z = zrow[c];
        const float val = yrow[c] * (z / (1.f + expf(-z)));
        v[j] = val;
        ss += val * val;
    }
#pragma unroll
    for (int o = 16; o; o >>= 1) ss += __shfl_xor_sync(0xffffffffu, ss, o);
    __shared__ float red[8];
    if ((tid & 31) == 0) red[tid >> 5] = ss;
    __syncthreads();
    float tot = 0.f;
#pragma unroll
    for (int i = 0; i < 8; i++) tot += red[i];
    const float scale = rsqrtf(tot * (1.f / (float)DIN) + 1e-5f);
#pragma unroll
    for (int j = 0; j < 8; j++) {
        const int c = tid + j * 256;
        hrow[c] = __float2half(v[j] * scale * norm_w[c]);
    }
}

// ---------------- launch ----------------
extern "C" void kernel_launch(void* const* d_in, const int* in_sizes, int n_in,
                              void* d_out, int out_size)
{
    (void)in_sizes; (void)n_in; (void)out_size;

    const float* hidden  = (const float*)d_in[0];
    const float* W_in    = (const float*)d_in[1];
    const float* conv_w  = (const float*)d_in[2];
    const float* conv_b  = (const float*)d_in[3];
    const float* dt_bias = (const float*)d_in[4];
    const float* A_log   = (const float*)d_in[5];
    const float* Dvec    = (const float*)d_in[6];
    const float* norm_w  = (const float*)d_in[7];
    const float* W_out   = (const float*)d_in[8];
    float* out = (float*)d_out;

    static float* zx = nullptr;
    static __half *ah, *w1h, *yh, *w2h;
    if (!zx) {
        void* p;
        cudaGetSymbolAddress(&p, g_zxbcdt); zx  = (float*)p;
        cudaGetSymbolAddress(&p, g_ah);   ah  = (__half*)p;
        cudaGetSymbolAddress(&p, g_w1h);  w1h = (__half*)p;
        cudaGetSymbolAddress(&p, g_yh);   yh  = (__half*)p;
        cudaGetSymbolAddress(&p, g_w2h);  w2h = (__half*)p;
        cudaFuncSetAttribute(gemm_hmma, cudaFuncAttributeMaxDynamicSharedMemorySize, GS_DYN);
        cudaFuncSetAttribute(ssd_chunk_kernel, cudaFuncAttributeMaxDynamicSharedMemorySize, SSD1_SMEM);
    }

    // 0) operand prep (fp16)
    {
        const int n4 = MROWS * DMODEL / 4;
        convert_h<<<(n4 + 255) / 256, 256>>>(hidden, ah, n4);
    }
    transpose_h<<<dim3(DPROJ / 32, DMODEL / 32), 256>>>(W_in, w1h, DMODEL, DPROJ);
    transpose_h<<<dim3(DMODEL / 32, DIN / 32), 256>>>(W_out, w2h, DIN, DMODEL);

    // 1) zxbcdt = hidden @ W_in
    gemm_hmma<<<dim3((DPROJ + 127) / 128, MROWS / 128), 256, GS_DYN>>>(
        ah, w1h, zx, DPROJ, DMODEL);

    // 2) conv + silu, dt/ldA
    conv_kernel<<<MROWS / 8, 256>>>(conv_w, conv_b);
    dt_kernel<<<MROWS * NH / 256, 256>>>(dt_bias, A_log);

    // 3) SSD
    ssd_chunk_kernel<<<dim3(NCHUNK, NH, BB), 256, SSD1_SMEM>>>(Dvec);
    ssd_state_kernel<<<dim3(NH, BB), 256>>>();
    ssd_inter_kernel<<<dim3(NCHUNK, NH, BB), 256>>>();

    // 4) gating + rmsnorm -> fp16
    gate_norm_kernel<<<MROWS, 256>>>(norm_w);

    // 5) out = y @ W_out
    gemm_hmma<<<dim3(DMODEL / 128, MROWS / 128), 256, GS_DYN>>>(
        yh, w2h, out, DMODEL, DIN);
}